// round 1
// baseline (speedup 1.0000x reference)
#include <cuda_runtime.h>
#include <math.h>
#include <stdint.h>

#define BB 256
#define NN 256
#define DD 1024
#define SS 1024

// Scratch (allocation-free rule: __device__ globals)
__device__ float g_A[BB * SS];   // state @ Q^T   [256,1024]
__device__ float g_M[BB * NN];   // A @ K         [256,256]

// ---------------------------------------------------------------------------
// packed fp32x2 helpers (FFMA2 — only reachable via PTX fma.rn.f32x2)
// ---------------------------------------------------------------------------
__device__ __forceinline__ unsigned long long pack2(float x) {
    unsigned long long r;
    asm("mov.b64 %0, {%1, %1};" : "=l"(r) : "f"(x));
    return r;
}
__device__ __forceinline__ void fma2(unsigned long long& d,
                                     unsigned long long a,
                                     unsigned long long b) {
    asm("fma.rn.f32x2 %0, %1, %2, %0;" : "+l"(d) : "l"(a), "l"(b));
}

// ---------------------------------------------------------------------------
// zero context region
// ---------------------------------------------------------------------------
__global__ void zero_ctx_kernel(float* __restrict__ ctx) {
    ctx[blockIdx.x * 256 + threadIdx.x] = 0.0f;
}

// ---------------------------------------------------------------------------
// K1: A[b,s] = sum_t state[b,t] * Q[s,t]   (NT GEMM, 256x1024, K=1024)
// tile 32(b) x 64(s), 256 threads, thread tile 2x4, ktile 32
// ---------------------------------------------------------------------------
__global__ __launch_bounds__(256) void k1_state_Qt(const float* __restrict__ state,
                                                   const float* __restrict__ Q) {
    __shared__ float sa[32 * 33];
    __shared__ float sq[64 * 33];
    const int tx = threadIdx.x;
    const int brow = blockIdx.y * 32;
    const int scol = blockIdx.x * 64;
    const int tr = tx >> 4;   // 0..15 -> rows tr*2, tr*2+1
    const int tc = tx & 15;   // 0..15 -> cols tc*4..tc*4+3

    float acc[2][4] = {};
    for (int kt = 0; kt < SS; kt += 32) {
        for (int l = tx; l < 32 * 32; l += 256) {
            int r = l >> 5, c = l & 31;
            sa[r * 33 + c] = state[(size_t)(brow + r) * SS + kt + c];
        }
        for (int l = tx; l < 64 * 32; l += 256) {
            int r = l >> 5, c = l & 31;
            sq[r * 33 + c] = Q[(size_t)(scol + r) * SS + kt + c];
        }
        __syncthreads();
#pragma unroll
        for (int k = 0; k < 32; k++) {
            float a0 = sa[(tr * 2 + 0) * 33 + k];
            float a1 = sa[(tr * 2 + 1) * 33 + k];
            float q0 = sq[(tc * 4 + 0) * 33 + k];
            float q1 = sq[(tc * 4 + 1) * 33 + k];
            float q2 = sq[(tc * 4 + 2) * 33 + k];
            float q3 = sq[(tc * 4 + 3) * 33 + k];
            acc[0][0] += a0 * q0; acc[0][1] += a0 * q1;
            acc[0][2] += a0 * q2; acc[0][3] += a0 * q3;
            acc[1][0] += a1 * q0; acc[1][1] += a1 * q1;
            acc[1][2] += a1 * q2; acc[1][3] += a1 * q3;
        }
        __syncthreads();
    }
#pragma unroll
    for (int rr = 0; rr < 2; rr++)
#pragma unroll
        for (int cc = 0; cc < 4; cc++)
            g_A[(size_t)(brow + tr * 2 + rr) * SS + scol + tc * 4 + cc] = acc[rr][cc];
}

// ---------------------------------------------------------------------------
// K2: M[b,n] = sum_s A[b,s] * Kmat[s,n]   (NN GEMM, 256x256, K=1024)
// tile 32x32, 256 threads, thread tile 2x2, ktile 32
// ---------------------------------------------------------------------------
__global__ __launch_bounds__(256) void k2_A_K(const float* __restrict__ Kmat) {
    __shared__ float sa[32 * 33];
    __shared__ float sk[32 * 33];
    const int tx = threadIdx.x;
    const int brow = blockIdx.y * 32;
    const int ncol = blockIdx.x * 32;
    const int tr = tx >> 4;  // rows tr*2..
    const int tc = tx & 15;  // cols tc*2..

    float acc[2][2] = {};
    for (int kt = 0; kt < SS; kt += 32) {
        for (int l = tx; l < 32 * 32; l += 256) {
            int r = l >> 5, c = l & 31;
            sa[r * 33 + c] = g_A[(size_t)(brow + r) * SS + kt + c];
            sk[r * 33 + c] = Kmat[(size_t)(kt + r) * NN + ncol + c];
        }
        __syncthreads();
#pragma unroll
        for (int k = 0; k < 32; k++) {
            float a0 = sa[(tr * 2 + 0) * 33 + k];
            float a1 = sa[(tr * 2 + 1) * 33 + k];
            float b0 = sk[k * 33 + tc * 2 + 0];
            float b1 = sk[k * 33 + tc * 2 + 1];
            acc[0][0] += a0 * b0; acc[0][1] += a0 * b1;
            acc[1][0] += a1 * b0; acc[1][1] += a1 * b1;
        }
        __syncthreads();
    }
#pragma unroll
    for (int rr = 0; rr < 2; rr++)
#pragma unroll
        for (int cc = 0; cc < 2; cc++)
            g_M[(size_t)(brow + tr * 2 + rr) * NN + ncol + tc * 2 + cc] = acc[rr][cc];
}

// ---------------------------------------------------------------------------
// K3 (main, fused): per block (btile, i):
//   logits[32,1024] = M[btile rows, :] @ FV[i]       (f32x2 register GEMM, K=256)
//   row softmax over D=1024
//   W[i, b, :] store  +  ctx[i,:] += sum_b W*FV[i,b,:]
//
// 256 threads: rg = tid/64 (4 row groups of 8 rows), cg = tid%64
// thread cols: cg*4 + j*256 + {0..3}, j=0..3  (16 cols as 4 float4 slots)
// dyn smem: sM[32][256] | sFV[8][1024] (k-stage, reused as ctx partials) |
//           red[32][65] | rowmax[32] | rowinv[32]
// ---------------------------------------------------------------------------
#define K3_SMEM_FLOATS (8192 + 8192 + 32 * 65 + 32 + 32)
#define K3_SMEM_BYTES (K3_SMEM_FLOATS * 4)

__global__ __launch_bounds__(256, 1) void k3_main(const float* __restrict__ FV,
                                                  float* __restrict__ Wout,
                                                  float* __restrict__ ctx) {
    extern __shared__ float smem[];
    float* sM = smem;                 // 8192
    float* sFV = smem + 8192;         // 8192
    float* red = smem + 16384;        // 32*65 = 2080
    float* rowmax = smem + 16384 + 2080;  // 32
    float* rowinv = rowmax + 32;          // 32

    const int tx = threadIdx.x;
    const int bt = blockIdx.x;    // 0..7  (b tile)
    const int i = blockIdx.y;     // 0..255
    const int rg = tx >> 6;       // 0..3
    const int cg = tx & 63;       // 0..63

    // load M tile [32, 256] (rows bt*32..+31)
    for (int it = 0; it < 8; it++) {
        int lf = tx + 256 * it;          // float4 index, 2048 total
        int r = lf >> 6, c4 = lf & 63;
        *(float4*)&sM[r * 256 + c4 * 4] =
            *(const float4*)&g_M[(size_t)(bt * 32 + r) * 256 + c4 * 4];
    }

    unsigned long long acc[64];  // [8 rows][8 f32x2] = 32x16 fp32 logits
#pragma unroll
    for (int q = 0; q < 64; q++) acc[q] = 0ull;

    const size_t ibase = (size_t)i * 256;

    // K loop over n = 0..255 in chunks of 8 (staged FV rows)
    for (int nt = 0; nt < 32; nt++) {
        const int kk0 = nt * 8;
        // stage FV[i, kk0..kk0+7, :]  (8x1024 floats = 2048 float4)
        for (int it = 0; it < 8; it++) {
            int lf = tx + 256 * it;
            int r = lf >> 8, c4 = lf & 255;
            *(float4*)&sFV[r * 1024 + c4 * 4] =
                *(const float4*)&FV[(ibase + kk0 + r) * 1024 + c4 * 4];
        }
        __syncthreads();
#pragma unroll
        for (int nk = 0; nk < 8; nk++) {
            unsigned long long mp[8];
#pragma unroll
            for (int r = 0; r < 8; r++)
                mp[r] = pack2(sM[(rg * 8 + r) * 256 + kk0 + nk]);
#pragma unroll
            for (int j = 0; j < 4; j++) {
                ulonglong2 f = *(const ulonglong2*)&sFV[nk * 1024 + cg * 4 + j * 256];
#pragma unroll
                for (int r = 0; r < 8; r++) {
                    fma2(acc[r * 8 + 2 * j + 0], mp[r], f.x);
                    fma2(acc[r * 8 + 2 * j + 1], mp[r], f.y);
                }
            }
        }
        __syncthreads();
    }

    float* af = reinterpret_cast<float*>(acc);  // af[r*16 + 4*j + e] -> col cg*4+j*256+e

    // ---- softmax over D per row ----
#pragma unroll
    for (int r = 0; r < 8; r++) {
        float m = af[r * 16];
#pragma unroll
        for (int q = 1; q < 16; q++) m = fmaxf(m, af[r * 16 + q]);
        red[(rg * 8 + r) * 65 + cg] = m;
    }
    __syncthreads();
    if (tx < 32) {
        float m = red[tx * 65];
        for (int c = 1; c < 64; c++) m = fmaxf(m, red[tx * 65 + c]);
        rowmax[tx] = m;
    }
    __syncthreads();
#pragma unroll
    for (int r = 0; r < 8; r++) {
        float rm = rowmax[rg * 8 + r];
        float s = 0.0f;
#pragma unroll
        for (int q = 0; q < 16; q++) {
            float e = __expf(af[r * 16 + q] - rm);
            af[r * 16 + q] = e;
            s += e;
        }
        red[(rg * 8 + r) * 65 + cg] = s;
    }
    __syncthreads();
    if (tx < 32) {
        float s = 0.0f;
        for (int c = 0; c < 64; c++) s += red[tx * 65 + c];
        rowinv[tx] = 1.0f / s;
    }
    __syncthreads();

    // ---- write W, accumulate context partials ----
    float part[16];
#pragma unroll
    for (int q = 0; q < 16; q++) part[q] = 0.0f;

#pragma unroll
    for (int r = 0; r < 8; r++) {
        const int b = bt * 32 + rg * 8 + r;
        const float inv = rowinv[rg * 8 + r];
        const float* fvrow = FV + (ibase + b) * 1024;
        float* wrow = Wout + (ibase + b) * 1024;
#pragma unroll
        for (int j = 0; j < 4; j++) {
            const int c = cg * 4 + j * 256;
            float4 w4;
            w4.x = af[r * 16 + 4 * j + 0] * inv;
            w4.y = af[r * 16 + 4 * j + 1] * inv;
            w4.z = af[r * 16 + 4 * j + 2] * inv;
            w4.w = af[r * 16 + 4 * j + 3] * inv;
            *(float4*)&wrow[c] = w4;
            float4 fv4 = *(const float4*)&fvrow[c];
            part[4 * j + 0] += w4.x * fv4.x;
            part[4 * j + 1] += w4.y * fv4.y;
            part[4 * j + 2] += w4.z * fv4.z;
            part[4 * j + 3] += w4.w * fv4.w;
        }
    }

    // cross-rowgroup reduce via sFV scratch (GEMM is done with it)
#pragma unroll
    for (int j = 0; j < 4; j++) {
        *(float4*)&sFV[rg * 1024 + cg * 4 + j * 256] =
            make_float4(part[4 * j], part[4 * j + 1], part[4 * j + 2], part[4 * j + 3]);
    }
    __syncthreads();
    for (int l = tx; l < 1024; l += 256) {
        float s = sFV[l] + sFV[1024 + l] + sFV[2048 + l] + sFV[3072 + l];
        atomicAdd(&ctx[(size_t)i * 1024 + l], s);
    }
}

// ---------------------------------------------------------------------------
extern "C" void kernel_launch(void* const* d_in, const int* in_sizes, int n_in,
                              void* d_out, int out_size) {
    const float* FV = (const float*)d_in[0];     // [256,256,1024]
    const float* state = (const float*)d_in[1];  // [256,1024]
    const float* Q = (const float*)d_in[2];      // [1024,1024]
    const float* Kmat = (const float*)d_in[3];   // [1024,256]

    float* out = (float*)d_out;
    float* ctx = out;                  // [256,1024]
    float* W = out + BB * DD;          // [256,256,1024]

    cudaFuncSetAttribute(k3_main, cudaFuncAttributeMaxDynamicSharedMemorySize,
                         K3_SMEM_BYTES);

    zero_ctx_kernel<<<1024, 256>>>(ctx);
    k1_state_Qt<<<dim3(16, 8), 256>>>(state, Q);
    k2_A_K<<<dim3(8, 8), 256>>>(Kmat);
    k3_main<<<dim3(8, 256), 256, K3_SMEM_BYTES>>>(FV, W, ctx);
}